// round 2
// baseline (speedup 1.0000x reference)
#include <cuda_runtime.h>

#define N_NODES 100000
#define E_EDGES 500000
#define KDIM    256      // latent
#define HID     256      // hidden
#define OUTD    128      // edge_dim

// Scratch (device globals — no allocation allowed)
__device__ float g_UV[(size_t)N_NODES * 512];   // per node: U[0:256], V[256:512]
__device__ float g_B[256 * 512];                // B[k][j]: layer-1 weights, K-major
__device__ float g_W2T[256 * 128];              // W2T[k][n]
__device__ int   g_idx64;                       // 1 if edge_index is int64

typedef unsigned long long u64;

__device__ __forceinline__ u64 pk2(float x, float y) {
    u64 lo = (u64)__float_as_uint(x);
    u64 hi = (u64)__float_as_uint(y);
    return (hi << 32) | lo;
}
__device__ __forceinline__ float2 up2(u64 v) {
    float2 r;
    r.x = __uint_as_float((unsigned)v);
    r.y = __uint_as_float((unsigned)(v >> 32));
    return r;
}
// Packed dual fp32 FMA (Blackwell f32x2 pipe — 2x FFMA throughput)
__device__ __forceinline__ void ffma2(u64 &d, u64 a, u64 b) {
    asm("fma.rn.f32x2 %0, %1, %2, %0;" : "+l"(d) : "l"(a), "l"(b));
}

// ---------------------------------------------------------------------------
// Detect edge_index dtype: int64 -> all odd 32-bit words of first 256 slots
// are zero (values < 2^31). int32 -> odd words are edge indices (~never all 0).
// ---------------------------------------------------------------------------
__global__ void detect_kernel(const unsigned* __restrict__ ei) {
    if (threadIdx.x == 0 && blockIdx.x == 0) {
        int ok = 1;
        #pragma unroll 1
        for (int i = 0; i < 256; i++)
            if (ei[2 * i + 1] != 0u) { ok = 0; break; }
        g_idx64 = ok;
    }
}

// ---------------------------------------------------------------------------
// Prep: permute W1 -> g_B (K-major, U cols 0..255, V cols 256..511), W2 -> W2T
// ---------------------------------------------------------------------------
__global__ void prep_kernel(const float* __restrict__ W1, const float* __restrict__ W2) {
    int idx = blockIdx.x * blockDim.x + threadIdx.x;
    if (idx < 256 * 512) {
        int k = idx >> 9;
        int j = idx & 511;
        float v = (j < 256) ? W1[j * 512 + k] : W1[(j - 256) * 512 + 256 + k];
        g_B[idx] = v;
    }
    if (idx < 256 * 128) {
        int k = idx >> 7;
        int n = idx & 127;
        g_W2T[idx] = W2[n * 256 + k];
    }
}

// ---------------------------------------------------------------------------
// Node GEMM: UV[N,512] = Z[N,256] @ g_B[256,512]
// 128x128 tile, BK=16, 8x8 per thread, f32x2 packed FMA
// ---------------------------------------------------------------------------
#define BK 16
#define APAD 132

__global__ void __launch_bounds__(256) node_gemm(const float* __restrict__ Z) {
    __shared__ float As[BK][APAD];   // [k][m] transposed
    __shared__ float Bs[BK][128];    // [k][n]

    const int tid = threadIdx.x;
    const int ty = tid >> 4, tx = tid & 15;
    const int rowbase = blockIdx.x * 128;
    const int colbase = blockIdx.y * 128;

    const int a_row = tid >> 2;            // 0..63
    const int a_k4  = (tid & 3) << 2;      // 0,4,8,12
    const int b_k   = tid >> 5;            // 0..7
    const int b_n   = (tid & 31) << 2;     // 0..124

    u64 acc[8][4];
    #pragma unroll
    for (int i = 0; i < 8; i++)
        #pragma unroll
        for (int j = 0; j < 4; j++) acc[i][j] = 0ull;

    for (int kc = 0; kc < 256; kc += BK) {
        #pragma unroll
        for (int p = 0; p < 2; p++) {
            int r = a_row + 64 * p;
            int gr = rowbase + r;
            gr = gr < N_NODES ? gr : N_NODES - 1;   // clamp; store is guarded
            float4 v = *reinterpret_cast<const float4*>(Z + (size_t)gr * 256 + kc + a_k4);
            As[a_k4 + 0][r] = v.x;
            As[a_k4 + 1][r] = v.y;
            As[a_k4 + 2][r] = v.z;
            As[a_k4 + 3][r] = v.w;
        }
        #pragma unroll
        for (int p = 0; p < 2; p++) {
            int k = b_k + 8 * p;
            *reinterpret_cast<float4*>(&Bs[k][b_n]) =
                *reinterpret_cast<const float4*>(g_B + (size_t)(kc + k) * 512 + colbase + b_n);
        }
        __syncthreads();

        #pragma unroll
        for (int k = 0; k < BK; k++) {
            float4 a0 = *reinterpret_cast<const float4*>(&As[k][ty * 4]);
            float4 a1 = *reinterpret_cast<const float4*>(&As[k][64 + ty * 4]);
            float4 b0 = *reinterpret_cast<const float4*>(&Bs[k][tx * 4]);
            float4 b1 = *reinterpret_cast<const float4*>(&Bs[k][64 + tx * 4]);
            float av[8] = {a0.x, a0.y, a0.z, a0.w, a1.x, a1.y, a1.z, a1.w};
            u64 bp[4] = {pk2(b0.x, b0.y), pk2(b0.z, b0.w), pk2(b1.x, b1.y), pk2(b1.z, b1.w)};
            #pragma unroll
            for (int i = 0; i < 8; i++) {
                u64 ap = pk2(av[i], av[i]);
                #pragma unroll
                for (int j = 0; j < 4; j++) ffma2(acc[i][j], ap, bp[j]);
            }
        }
        __syncthreads();
    }

    #pragma unroll
    for (int i = 0; i < 8; i++) {
        int r = (i < 4) ? (ty * 4 + i) : (64 + ty * 4 + (i - 4));
        int gr = rowbase + r;
        if (gr < N_NODES) {
            float* dst = g_UV + (size_t)gr * 512 + colbase;
            float2 p0 = up2(acc[i][0]), p1 = up2(acc[i][1]);
            float2 p2 = up2(acc[i][2]), p3 = up2(acc[i][3]);
            float4 v0 = {p0.x, p0.y, p1.x, p1.y};
            float4 v1 = {p2.x, p2.y, p3.x, p3.y};
            *reinterpret_cast<float4*>(dst + tx * 4) = v0;
            *reinterpret_cast<float4*>(dst + 64 + tx * 4) = v1;
        }
    }
}

// ---------------------------------------------------------------------------
// Edge kernel: out[e,:] = relu(U[src]+V[dst]+b1) @ W2T + b2
// 128 edges x 128 outs per block, gather fused into A-tile stage
// ---------------------------------------------------------------------------
__global__ void __launch_bounds__(256) edge_mlp(const void* __restrict__ EI,
                                                const float* __restrict__ b1,
                                                const float* __restrict__ b2,
                                                float* __restrict__ out) {
    __shared__ float As[BK][APAD];   // h[k][edge]
    __shared__ float Bs[BK][128];    // W2T chunk
    __shared__ int s_src[128], s_dst[128];

    const int tid = threadIdx.x;
    const int ty = tid >> 4, tx = tid & 15;
    const int ebase = blockIdx.x * 128;

    if (tid < 128) {
        int e = ebase + tid;
        long long s = 0, d = 0;
        if (e < E_EDGES) {
            if (g_idx64) {
                const long long* p = (const long long*)EI;
                s = p[e];
                d = p[E_EDGES + e];
            } else {
                const int* p = (const int*)EI;
                s = p[e];
                d = p[E_EDGES + e];
            }
        }
        int si = (int)s, di = (int)d;
        si = min(max(si, 0), N_NODES - 1);
        di = min(max(di, 0), N_NODES - 1);
        s_src[tid] = si;
        s_dst[tid] = di;
    }
    __syncthreads();

    const int g_e  = tid >> 2;           // 0..63
    const int g_k4 = (tid & 3) << 2;     // 0,4,8,12
    const int b_k  = tid >> 5;
    const int b_n  = (tid & 31) << 2;

    u64 acc[8][4];
    #pragma unroll
    for (int i = 0; i < 8; i++)
        #pragma unroll
        for (int j = 0; j < 4; j++) acc[i][j] = 0ull;

    for (int kc = 0; kc < 256; kc += BK) {
        float4 bb = *reinterpret_cast<const float4*>(b1 + kc + g_k4);
        #pragma unroll
        for (int p = 0; p < 2; p++) {
            int e = g_e + 64 * p;
            const float4 u = *reinterpret_cast<const float4*>(
                g_UV + (size_t)s_src[e] * 512 + kc + g_k4);
            const float4 v = *reinterpret_cast<const float4*>(
                g_UV + (size_t)s_dst[e] * 512 + 256 + kc + g_k4);
            As[g_k4 + 0][e] = fmaxf(u.x + v.x + bb.x, 0.f);
            As[g_k4 + 1][e] = fmaxf(u.y + v.y + bb.y, 0.f);
            As[g_k4 + 2][e] = fmaxf(u.z + v.z + bb.z, 0.f);
            As[g_k4 + 3][e] = fmaxf(u.w + v.w + bb.w, 0.f);
        }
        #pragma unroll
        for (int p = 0; p < 2; p++) {
            int k = b_k + 8 * p;
            *reinterpret_cast<float4*>(&Bs[k][b_n]) =
                *reinterpret_cast<const float4*>(g_W2T + (size_t)(kc + k) * 128 + b_n);
        }
        __syncthreads();

        #pragma unroll
        for (int k = 0; k < BK; k++) {
            float4 a0 = *reinterpret_cast<const float4*>(&As[k][ty * 4]);
            float4 a1 = *reinterpret_cast<const float4*>(&As[k][64 + ty * 4]);
            float4 b0 = *reinterpret_cast<const float4*>(&Bs[k][tx * 4]);
            float4 b1v = *reinterpret_cast<const float4*>(&Bs[k][64 + tx * 4]);
            float av[8] = {a0.x, a0.y, a0.z, a0.w, a1.x, a1.y, a1.z, a1.w};
            u64 bp[4] = {pk2(b0.x, b0.y), pk2(b0.z, b0.w), pk2(b1v.x, b1v.y), pk2(b1v.z, b1v.w)};
            #pragma unroll
            for (int i = 0; i < 8; i++) {
                u64 ap = pk2(av[i], av[i]);
                #pragma unroll
                for (int j = 0; j < 4; j++) ffma2(acc[i][j], ap, bp[j]);
            }
        }
        __syncthreads();
    }

    float4 c0 = *reinterpret_cast<const float4*>(b2 + tx * 4);
    float4 c1 = *reinterpret_cast<const float4*>(b2 + 64 + tx * 4);
    #pragma unroll
    for (int i = 0; i < 8; i++) {
        int r = (i < 4) ? (ty * 4 + i) : (64 + ty * 4 + (i - 4));
        int e = ebase + r;
        if (e < E_EDGES) {
            float* dst = out + (size_t)e * 128;
            float2 p0 = up2(acc[i][0]), p1 = up2(acc[i][1]);
            float2 p2 = up2(acc[i][2]), p3 = up2(acc[i][3]);
            float4 v0 = {p0.x + c0.x, p0.y + c0.y, p1.x + c0.z, p1.y + c0.w};
            float4 v1 = {p2.x + c1.x, p2.y + c1.y, p3.x + c1.z, p3.y + c1.w};
            *reinterpret_cast<float4*>(dst + tx * 4) = v0;
            *reinterpret_cast<float4*>(dst + 64 + tx * 4) = v1;
        }
    }
}

// ---------------------------------------------------------------------------
// Inputs resolved by UNIQUE element counts (robust to metadata ordering):
//   z: 25,600,000   edge_index: 1,000,000   W1: 131,072
//   W2: 32,768      b1: 256                 b2: 128
// ---------------------------------------------------------------------------
extern "C" void kernel_launch(void* const* d_in, const int* in_sizes, int n_in,
                              void* d_out, int out_size) {
    const float* z  = nullptr;
    const void*  ei = nullptr;
    const float* W1 = nullptr;
    const float* b1 = nullptr;
    const float* W2 = nullptr;
    const float* b2 = nullptr;

    for (int i = 0; i < n_in; i++) {
        switch (in_sizes[i]) {
            case 25600000: z  = (const float*)d_in[i]; break;
            case 1000000:  ei = d_in[i];               break;
            case 131072:   W1 = (const float*)d_in[i]; break;
            case 256:      b1 = (const float*)d_in[i]; break;
            case 32768:    W2 = (const float*)d_in[i]; break;
            case 128:      b2 = (const float*)d_in[i]; break;
            default: break;
        }
    }

    float* out = (float*)d_out;

    detect_kernel<<<1, 32>>>((const unsigned*)ei);
    prep_kernel<<<640, 256>>>(W1, W2);
    node_gemm<<<dim3((N_NODES + 127) / 128, 4), 256>>>(z);
    edge_mlp<<<(E_EDGES + 127) / 128, 256>>>(ei, b1, b2, out);
}

// round 5
// speedup vs baseline: 1.8191x; 1.8191x over previous
#include <cuda_runtime.h>
#include <cuda_bf16.h>
#include <cstdint>

#define N_NODES 100000
#define E_EDGES 500000

// ---------------------------------------------------------------------------
// Device scratch
// ---------------------------------------------------------------------------
__device__ float g_UV[(size_t)N_NODES * 512];   // per node: U[0:256], V[256:512]
__device__ uint4 g_nBhi4[16384];                // node B: 8 chunks x 128x128 bf16
__device__ uint4 g_nBlo4[16384];
__device__ uint4 g_eBhi4[4096];                 // edge B (W2): 2 chunks x 128x128 bf16
__device__ uint4 g_eBlo4[4096];
__device__ int   g_idx64;

// chunk stride in uint4 units: 128*128 bf16 = 32768 B = 2048 uint4
#define CHUNK_U4 2048

// smem layout (bytes)
#define OFF_SRC  0
#define OFF_DST  512
#define OFF_AHI  1024
#define OFF_ALO  (1024 + 67584)
#define OFF_BHI  (1024 + 2 * 67584)
#define OFF_BLO  (1024 + 2 * 67584 + 34816)
#define SM_BYTES (1024 + 2 * 67584 + 2 * 34816)   // 205824
#define PITCH_A  528    // bytes per A row (264 bf16: 256 + 8 pad)
#define PITCH_B  272    // bytes per B row (136 bf16: 128 + 8 pad)

__device__ __forceinline__ uint32_t smem_u32(const void* p) {
    uint32_t a;
    asm("{ .reg .u64 t; cvta.to.shared.u64 t, %1; cvt.u32.u64 %0, t; }" : "=r"(a) : "l"(p));
    return a;
}

__device__ __forceinline__ void ldsm_x4(uint32_t* r, uint32_t addr) {
    asm volatile("ldmatrix.sync.aligned.m8n8.x4.shared.b16 {%0,%1,%2,%3}, [%4];"
                 : "=r"(r[0]), "=r"(r[1]), "=r"(r[2]), "=r"(r[3]) : "r"(addr));
}

__device__ __forceinline__ void mma16816(float* d, const uint32_t* a, const uint32_t* b) {
    asm volatile(
        "mma.sync.aligned.m16n8k16.row.col.f32.bf16.bf16.f32 "
        "{%0,%1,%2,%3},{%4,%5,%6,%7},{%8,%9},{%0,%1,%2,%3};"
        : "+f"(d[0]), "+f"(d[1]), "+f"(d[2]), "+f"(d[3])
        : "r"(a[0]), "r"(a[1]), "r"(a[2]), "r"(a[3]), "r"(b[0]), "r"(b[1]));
}

__device__ __forceinline__ void split2(float a, float b, uint32_t& hi, uint32_t& lo) {
    __nv_bfloat16 ah = __float2bfloat16_rn(a);
    __nv_bfloat16 bh = __float2bfloat16_rn(b);
    __nv_bfloat16 al = __float2bfloat16_rn(a - __bfloat162float(ah));
    __nv_bfloat16 bl = __float2bfloat16_rn(b - __bfloat162float(bh));
    hi = (uint32_t)__bfloat16_as_ushort(ah) | ((uint32_t)__bfloat16_as_ushort(bh) << 16);
    lo = (uint32_t)__bfloat16_as_ushort(al) | ((uint32_t)__bfloat16_as_ushort(bl) << 16);
}

// ---------------------------------------------------------------------------
// detect edge_index dtype (int64 vs int32)
// ---------------------------------------------------------------------------
__global__ void detect_kernel(const unsigned* __restrict__ ei) {
    if (threadIdx.x == 0 && blockIdx.x == 0) {
        int ok = 1;
        #pragma unroll 1
        for (int i = 0; i < 256; i++)
            if (ei[2 * i + 1] != 0u) { ok = 0; break; }
        g_idx64 = ok;
    }
}

// ---------------------------------------------------------------------------
// prep: split weights into bf16 hi/lo chunk blobs [chunk][row][k] (128x128)
//   node B row j (0..511): j<256 -> W1[j][k], else W1[j-256][256+k]; chunk = kc*4+nc
//   edge B = W2[n][k]; chunk = kc
// ---------------------------------------------------------------------------
__global__ void prep_kernel(const float* __restrict__ W1, const float* __restrict__ W2) {
    int idx = blockIdx.x * blockDim.x + threadIdx.x;
    float v;
    uint32_t off;
    __nv_bfloat16 *dh, *dl;
    if (idx < 131072) {
        int j = idx >> 8, k = idx & 255;
        v = (j < 256) ? W1[j * 512 + k] : W1[(j - 256) * 512 + 256 + k];
        int nc = j >> 7, row = j & 127, kc = k >> 7, kp = k & 127;
        off = (uint32_t)(kc * 4 + nc) * 16384u + row * 128 + kp;
        dh = (__nv_bfloat16*)g_nBhi4; dl = (__nv_bfloat16*)g_nBlo4;
    } else {
        int e = idx - 131072;
        if (e >= 32768) return;
        int n = e >> 8, k = e & 255;
        v = W2[n * 256 + k];
        int kc = k >> 7, kp = k & 127;
        off = (uint32_t)kc * 16384u + n * 128 + kp;
        dh = (__nv_bfloat16*)g_eBhi4; dl = (__nv_bfloat16*)g_eBlo4;
    }
    __nv_bfloat16 h = __float2bfloat16_rn(v);
    dh[off] = h;
    dl[off] = __float2bfloat16_rn(v - __bfloat162float(h));
}

// ---------------------------------------------------------------------------
// shared device helpers for the MMA kernels
// ---------------------------------------------------------------------------
// copy one 128x128 bf16 chunk (hi+lo) from gmem blobs into padded smem B tiles
__device__ __forceinline__ void load_B_chunk(char* sm, const uint4* srcH, const uint4* srcL,
                                             int tid) {
    const int off16 = tid & 15;           // 16B unit within 256B row
    #pragma unroll
    for (int i = 0; i < 8; i++) {
        int row = i * 16 + (tid >> 4);
        uint4 h = srcH[row * 16 + off16];
        uint4 l = srcL[row * 16 + off16];
        *(uint4*)(sm + OFF_BHI + row * PITCH_B + off16 * 16) = h;
        *(uint4*)(sm + OFF_BLO + row * PITCH_B + off16 * 16) = l;
    }
}

// run 8 k-steps of 3-pass bf16 mma over one 128-k chunk
__device__ __forceinline__ void mma_chunk(float d[4][4][4],
                                          uint32_t aHiBase, uint32_t aLoBase,
                                          uint32_t bHiBase, uint32_t bLoBase) {
    #pragma unroll 1
    for (int ks = 0; ks < 8; ks++) {
        uint32_t Ah[4][4], Al[4][4], Bh[2][4], Bl[2][4];
        #pragma unroll
        for (int f = 0; f < 4; f++) {
            ldsm_x4(Ah[f], aHiBase + f * (16 * PITCH_A) + ks * 32);
            ldsm_x4(Al[f], aLoBase + f * (16 * PITCH_A) + ks * 32);
        }
        #pragma unroll
        for (int gp = 0; gp < 2; gp++) {
            ldsm_x4(Bh[gp], bHiBase + gp * (16 * PITCH_B) + ks * 32);
            ldsm_x4(Bl[gp], bLoBase + gp * (16 * PITCH_B) + ks * 32);
        }
        #pragma unroll
        for (int f = 0; f < 4; f++)
            #pragma unroll
            for (int g = 0; g < 4; g++) {
                const uint32_t* bh = &Bh[g >> 1][(g & 1) * 2];
                const uint32_t* bl = &Bl[g >> 1][(g & 1) * 2];
                mma16816(d[f][g], Ah[f], bh);
                mma16816(d[f][g], Ah[f], bl);
                mma16816(d[f][g], Al[f], bh);
            }
    }
}

// per-lane ldmatrix base addresses inside A / B tiles
__device__ __forceinline__ uint32_t a_lane_base(uint32_t smA, int wm, int lane) {
    int row = wm * 64 + (lane & 7) + ((lane >> 3) & 1) * 8;
    return smA + row * PITCH_A + ((lane >> 4) & 1) * 16;
}
__device__ __forceinline__ uint32_t b_lane_base(uint32_t smB, int wn, int lane) {
    int n = wn * 32 + (lane & 7) + ((lane >> 4) & 1) * 8;
    return smB + n * PITCH_B + ((lane >> 3) & 1) * 16;
}

// ---------------------------------------------------------------------------
// node kernel: UV[tile of 128 nodes, 512] = Z @ B^T (3-pass bf16 mma.sync)
// ---------------------------------------------------------------------------
__global__ void __launch_bounds__(256, 1) node_mma(const float* __restrict__ Z) {
    extern __shared__ char sm[];
    const uint32_t smb = smem_u32(sm);
    const int tid = threadIdx.x, lane = tid & 31, wid = tid >> 5;
    const int wm = wid & 1, wn = wid >> 1;
    const int mbase = blockIdx.x * 128;

    // --- stage A: load Z rows, split to bf16 hi/lo, full K=256 resident ---
    {
        const int lrow = tid >> 3;          // 0..31 per sweep
        const int lk = (tid & 7) * 4;       // float offset
        #pragma unroll 1
        for (int s = 0; s < 4; s++) {
            int row = s * 32 + lrow;
            int gr = min(mbase + row, N_NODES - 1);
            const float* zr = Z + (size_t)gr * 256;
            char* ah = sm + OFF_AHI + row * PITCH_A;
            char* al = sm + OFF_ALO + row * PITCH_A;
            #pragma unroll
            for (int i = 0; i < 8; i++) {
                int k = lk + i * 32;
                float4 z4 = *(const float4*)(zr + k);
                uint32_t h0, l0, h1, l1;
                split2(z4.x, z4.y, h0, l0);
                split2(z4.z, z4.w, h1, l1);
                *(uint2*)(ah + k * 2) = make_uint2(h0, h1);
                *(uint2*)(al + k * 2) = make_uint2(l0, l1);
            }
        }
    }
    __syncthreads();

    const uint32_t aHi = a_lane_base(smb + OFF_AHI, wm, lane);
    const uint32_t aLo = a_lane_base(smb + OFF_ALO, wm, lane);
    const uint32_t bHi = b_lane_base(smb + OFF_BHI, wn, lane);
    const uint32_t bLo = b_lane_base(smb + OFF_BLO, wn, lane);

    #pragma unroll 1
    for (int nc = 0; nc < 4; nc++) {
        float d[4][4][4];
        #pragma unroll
        for (int f = 0; f < 4; f++)
            #pragma unroll
            for (int g = 0; g < 4; g++)
                #pragma unroll
                for (int c = 0; c < 4; c++) d[f][g][c] = 0.f;

        #pragma unroll 1
        for (int kc = 0; kc < 2; kc++) {
            load_B_chunk(sm, g_nBhi4 + (kc * 4 + nc) * CHUNK_U4,
                             g_nBlo4 + (kc * 4 + nc) * CHUNK_U4, tid);
            __syncthreads();
            mma_chunk(d, aHi + kc * 256, aLo + kc * 256, bHi, bLo);
            __syncthreads();
        }

        // epilogue: write 128x128 block to g_UV
        #pragma unroll
        for (int g = 0; g < 4; g++) {
            int col = nc * 128 + wn * 32 + g * 8 + (lane & 3) * 2;
            #pragma unroll
            for (int f = 0; f < 4; f++) {
                int r0 = mbase + wm * 64 + f * 16 + (lane >> 2);
                if (r0 < N_NODES)
                    *(float2*)(g_UV + (size_t)r0 * 512 + col) =
                        make_float2(d[f][g][0], d[f][g][1]);
                int r1 = r0 + 8;
                if (r1 < N_NODES)
                    *(float2*)(g_UV + (size_t)r1 * 512 + col) =
                        make_float2(d[f][g][2], d[f][g][3]);
            }
        }
    }
}

// ---------------------------------------------------------------------------
// edge kernel: out[128 edges, 128] = relu(U[src]+V[dst]+b1) @ W2^T + b2
// ---------------------------------------------------------------------------
__global__ void __launch_bounds__(256, 1) edge_mma(const void* __restrict__ EI,
                                                   const float* __restrict__ b1,
                                                   const float* __restrict__ b2,
                                                   float* __restrict__ out) {
    extern __shared__ char sm[];
    const uint32_t smb = smem_u32(sm);
    int* ssrc = (int*)(sm + OFF_SRC);
    int* sdst = (int*)(sm + OFF_DST);
    const int tid = threadIdx.x, lane = tid & 31, wid = tid >> 5;
    const int wm = wid & 1, wn = wid >> 1;
    const int ebase = blockIdx.x * 128;

    if (tid < 128) {
        int e = ebase + tid;
        long long s = 0, dd = 0;
        if (e < E_EDGES) {
            if (g_idx64) {
                const long long* p = (const long long*)EI;
                s = p[e]; dd = p[E_EDGES + e];
            } else {
                const int* p = (const int*)EI;
                s = p[e]; dd = p[E_EDGES + e];
            }
        }
        ssrc[tid] = min(max((int)s, 0), N_NODES - 1);
        sdst[tid] = min(max((int)dd, 0), N_NODES - 1);
    }
    __syncthreads();

    // --- stage A: gather U[src]+V[dst]+b1, relu, split, full K=256 ---
    {
        const int lrow = tid >> 3;
        const int lk = (tid & 7) * 4;
        #pragma unroll 1
        for (int s = 0; s < 4; s++) {
            int row = s * 32 + lrow;
            const float* Ur = g_UV + (size_t)ssrc[row] * 512;
            const float* Vr = g_UV + (size_t)sdst[row] * 512 + 256;
            char* ah = sm + OFF_AHI + row * PITCH_A;
            char* al = sm + OFF_ALO + row * PITCH_A;
            #pragma unroll
            for (int i = 0; i < 8; i++) {
                int k = lk + i * 32;
                float4 u4 = *(const float4*)(Ur + k);
                float4 v4 = *(const float4*)(Vr + k);
                float4 c4 = *(const float4*)(b1 + k);
                float h0 = fmaxf(u4.x + v4.x + c4.x, 0.f);
                float h1 = fmaxf(u4.y + v4.y + c4.y, 0.f);
                float h2 = fmaxf(u4.z + v4.z + c4.z, 0.f);
                float h3 = fmaxf(u4.w + v4.w + c4.w, 0.f);
                uint32_t H0, L0, H1, L1;
                split2(h0, h1, H0, L0);
                split2(h2, h3, H1, L1);
                *(uint2*)(ah + k * 2) = make_uint2(H0, H1);
                *(uint2*)(al + k * 2) = make_uint2(L0, L1);
            }
        }
    }
    __syncthreads();

    const uint32_t aHi = a_lane_base(smb + OFF_AHI, wm, lane);
    const uint32_t aLo = a_lane_base(smb + OFF_ALO, wm, lane);
    const uint32_t bHi = b_lane_base(smb + OFF_BHI, wn, lane);
    const uint32_t bLo = b_lane_base(smb + OFF_BLO, wn, lane);

    float d[4][4][4];
    #pragma unroll
    for (int f = 0; f < 4; f++)
        #pragma unroll
        for (int g = 0; g < 4; g++)
            #pragma unroll
            for (int c = 0; c < 4; c++) d[f][g][c] = 0.f;

    #pragma unroll 1
    for (int kc = 0; kc < 2; kc++) {
        load_B_chunk(sm, g_eBhi4 + kc * CHUNK_U4, g_eBlo4 + kc * CHUNK_U4, tid);
        __syncthreads();
        mma_chunk(d, aHi + kc * 256, aLo + kc * 256, bHi, bLo);
        __syncthreads();
    }

    // epilogue: + b2, write out
    #pragma unroll
    for (int g = 0; g < 4; g++) {
        int col = wn * 32 + g * 8 + (lane & 3) * 2;
        float bx = b2[col], by = b2[col + 1];
        #pragma unroll
        for (int f = 0; f < 4; f++) {
            int r0 = ebase + wm * 64 + f * 16 + (lane >> 2);
            if (r0 < E_EDGES)
                *(float2*)(out + (size_t)r0 * 128 + col) =
                    make_float2(d[f][g][0] + bx, d[f][g][1] + by);
            int r1 = r0 + 8;
            if (r1 < E_EDGES)
                *(float2*)(out + (size_t)r1 * 128 + col) =
                    make_float2(d[f][g][2] + bx, d[f][g][3] + by);
        }
    }
}

// ---------------------------------------------------------------------------
// launch — inputs resolved by unique element counts
// ---------------------------------------------------------------------------
extern "C" void kernel_launch(void* const* d_in, const int* in_sizes, int n_in,
                              void* d_out, int out_size) {
    const float* z = nullptr;
    const void* ei = nullptr;
    const float* W1 = nullptr;
    const float* b1 = nullptr;
    const float* W2 = nullptr;
    const float* b2 = nullptr;
    for (int i = 0; i < n_in; i++) {
        switch (in_sizes[i]) {
            case 25600000: z = (const float*)d_in[i]; break;
            case 1000000:  ei = d_in[i];              break;
            case 131072:   W1 = (const float*)d_in[i]; break;
            case 256:      b1 = (const float*)d_in[i]; break;
            case 32768:    W2 = (const float*)d_in[i]; break;
            case 128:      b2 = (const float*)d_in[i]; break;
            default: break;
        }
    }
    float* out = (float*)d_out;

    cudaFuncSetAttribute(node_mma, cudaFuncAttributeMaxDynamicSharedMemorySize, SM_BYTES);
    cudaFuncSetAttribute(edge_mma, cudaFuncAttributeMaxDynamicSharedMemorySize, SM_BYTES);

    detect_kernel<<<1, 32>>>((const unsigned*)ei);
    prep_kernel<<<640, 256>>>(W1, W2);
    node_mma<<<(N_NODES + 127) / 128, 256, SM_BYTES>>>(z);
    edge_mma<<<(E_EDGES + 127) / 128, 256, SM_BYTES>>>(ei, b1, b2, out);
}